// round 15
// baseline (speedup 1.0000x reference)
#include <cuda_runtime.h>
#include <cuda_bf16.h>
#include <cstdint>

#define BB   16
#define CC   256
#define IMG  4096
#define KTOT 2304

// ---------------- device scratch ----------------
__device__ float g_style1[BB*CC], g_style2[BB*CC];
__device__ float g_demod1[BB*CC], g_demod2[BB*CC];
__device__ float g_wsq1[CC*CC],  g_wsq2[CC*CC];           // [ci][co] sum_t w^2
__device__ __nv_bfloat16 g_w1h[CC*KTOT], g_w1l[CC*KTOT];  // [co][tap*256+ci]
__device__ __nv_bfloat16 g_w2h[CC*KTOT], g_w2l[CC*KTOT];
__device__ __nv_bfloat16 g_xh[(size_t)BB*IMG*CC], g_xl[(size_t)BB*IMG*CC]; // [b][px][ci]
__device__ __nv_bfloat16 g_hh[(size_t)BB*IMG*CC], g_hl[(size_t)BB*IMG*CC];

// ---------------- helpers ----------------
__device__ __forceinline__ uint32_t smem_u32(const void* p) {
    uint32_t a;
    asm("{ .reg .u64 t; cvta.to.shared.u64 t, %1; cvt.u32.u64 %0, t; }" : "=r"(a) : "l"(p));
    return a;
}
__device__ __forceinline__ void cp16(uint32_t dst, const void* src) {
    asm volatile("cp.async.cg.shared.global [%0], [%1], 16;" :: "r"(dst), "l"(src) : "memory");
}
__device__ __forceinline__ void cp16z(uint32_t dst, const void* src, uint32_t sz) {
    asm volatile("cp.async.cg.shared.global [%0], [%1], 16, %2;" :: "r"(dst), "l"(src), "r"(sz) : "memory");
}
#define CP_COMMIT() asm volatile("cp.async.commit_group;" ::: "memory")
#define CP_WAIT0()  asm volatile("cp.async.wait_group 0;" ::: "memory")

#define LDSM4(r, a) \
    asm volatile("ldmatrix.sync.aligned.m8n8.x4.shared.b16 {%0,%1,%2,%3}, [%4];" \
        : "=r"((r)[0]), "=r"((r)[1]), "=r"((r)[2]), "=r"((r)[3]) : "r"(a))

#define MMA16816(c, a, b0, b1) \
    asm volatile("mma.sync.aligned.m16n8k16.row.col.f32.bf16.bf16.f32 " \
        "{%0,%1,%2,%3},{%4,%5,%6,%7},{%8,%9},{%0,%1,%2,%3};" \
        : "+f"((c)[0]), "+f"((c)[1]), "+f"((c)[2]), "+f"((c)[3]) \
        : "r"((a)[0]), "r"((a)[1]), "r"((a)[2]), "r"((a)[3]), "r"(b0), "r"(b1))

// ---------------- style = (w/32) @ s_w^T + s_b ----------------
template<int L>
__global__ void style_kernel(const float* __restrict__ wv, const float* __restrict__ sw,
                             const float* __restrict__ sb) {
    const int b = blockIdx.x, c = threadIdx.x;
    __shared__ float sv[512];
    sv[c] = wv[b*512 + c]; sv[c+256] = wv[b*512 + 256 + c];
    __syncthreads();
    float acc = 0.f;
    const float4* row = (const float4*)(sw + (size_t)c*512);
#pragma unroll 8
    for (int q = 0; q < 128; ++q) {
        float4 w4 = row[q];
        acc += w4.x*sv[4*q] + w4.y*sv[4*q+1] + w4.z*sv[4*q+2] + w4.w*sv[4*q+3];
    }
    (L == 0 ? g_style1 : g_style2)[b*256 + c] = acc * 0.03125f + sb[c];
}

// ---------------- wsq[ci][co] = sum_t w[co][ci][t]^2 ----------------
template<int L>
__global__ void wsq_kernel(const float* __restrict__ w) {
    int co = blockIdx.x, ci = threadIdx.x;
    const float* p = w + (size_t)co*KTOT + ci*9;
    float a = 0.f;
#pragma unroll
    for (int t = 0; t < 9; ++t) a += p[t]*p[t];
    (L == 0 ? g_wsq1 : g_wsq2)[ci*256 + co] = a;
}

// ---------------- demod ----------------
template<int L>
__global__ void demod_kernel() {
    const float* style = (L == 0) ? g_style1 : g_style2;
    const float* wsq   = (L == 0) ? g_wsq1   : g_wsq2;
    float*       dm    = (L == 0) ? g_demod1 : g_demod2;
    const int b = blockIdx.x, co = threadIdx.x;
    __shared__ float s2[256];
    float sv = style[b*256 + co];
    s2[co] = sv*sv;
    __syncthreads();
    float acc = 0.f;
    for (int ci = 0; ci < 256; ++ci) acc += s2[ci] * wsq[ci*256 + co];
    dm[b*256 + co] = rsqrtf(acc + 1e-8f);
}

// ---------------- weight convert: [co][ci*9+tap] -> bf16 hi/lo [co][tap*256+ci] ----
template<int L>
__global__ void wcv_kernel(const float* __restrict__ w) {
    int i = blockIdx.x*256 + threadIdx.x;
    int co = i / KTOT;
    int r  = i - co*KTOT;
    int tap = r >> 8, ci = r & 255;
    float v = w[(size_t)co*KTOT + ci*9 + tap];
    __nv_bfloat16 h = __float2bfloat16(v);
    (L == 0 ? g_w1h : g_w2h)[i] = h;
    (L == 0 ? g_w1l : g_w2l)[i] = __float2bfloat16(v - __bfloat162float(h));
}

// ---------------- x transpose + modulate + bf16 split -> [b][px][ci] ----------------
__global__ void xt_kernel(const float* __restrict__ x) {
    __shared__ float s[64][65];
    const int px0 = blockIdx.x << 6, ci0 = blockIdx.y << 6, b = blockIdx.z;
    const int t = threadIdx.x;
    for (int i = t; i < 1024; i += 256) {
        int ci = i >> 4, q = i & 15;
        float4 v = ((const float4*)(x + (size_t)(b*CC + ci0 + ci)*IMG + px0))[q];
        float st = g_style1[b*CC + ci0 + ci];
        s[ci][q*4+0] = v.x*st; s[ci][q*4+1] = v.y*st;
        s[ci][q*4+2] = v.z*st; s[ci][q*4+3] = v.w*st;
    }
    __syncthreads();
    const int px_l = t >> 2, seg = t & 3;
    __align__(16) __nv_bfloat16 hb[16], lb[16];
#pragma unroll
    for (int k = 0; k < 16; ++k) {
        float v = s[seg*16 + k][px_l];
        __nv_bfloat16 h = __float2bfloat16(v);
        hb[k] = h;
        lb[k] = __float2bfloat16(v - __bfloat162float(h));
    }
    size_t o = (size_t)(b*IMG + px0 + px_l)*256 + ci0 + seg*16;
    ((uint4*)(g_xh + o))[0] = ((const uint4*)hb)[0];
    ((uint4*)(g_xh + o))[1] = ((const uint4*)hb)[1];
    ((uint4*)(g_xl + o))[0] = ((const uint4*)lb)[0];
    ((uint4*)(g_xl + o))[1] = ((const uint4*)lb)[1];
}

// ================= HMMA implicit-GEMM conv3x3, 2 CTAs/SM =================
// CTA: 128 co x 128 px, 256 threads (8 warps). K chunks of 32 ci, 72 iters.
// smem (99840 B): [0,128) zero | W 2x16K (hi 8K + lo 8K) | ACT halo 2x33024
#define Z_OFF    0
#define WT_OFF   1024
#define WT_STG   16384
#define WT_LO    8192
#define ACT_OFF  (WT_OFF + 2*WT_STG)          // 33792
#define ACT_STG  33024
#define ACT_LO   16512
#define SMEM_TOTAL (ACT_OFF + 2*ACT_STG)      // 99840

template<int LAYER>
__global__ void __launch_bounds__(256, 2)
conv_hmma(const float* __restrict__ noise, const float* __restrict__ nw,
          float* __restrict__ out) {
    extern __shared__ __align__(1024) char smem[];
    const uint32_t sb = smem_u32(smem);
    const int tid = threadIdx.x, lid = tid & 31, wid = tid >> 5;

    const int pxt = blockIdx.x << 7;
    const int co0 = blockIdx.y << 7;
    const int b   = blockIdx.z;

    const __nv_bfloat16* __restrict__ Ahp = (LAYER == 0) ? g_xh  : g_hh;
    const __nv_bfloat16* __restrict__ Alp = (LAYER == 0) ? g_xl  : g_hl;
    const __nv_bfloat16* __restrict__ Whp = (LAYER == 0) ? g_w1h : g_w2h;
    const __nv_bfloat16* __restrict__ Wlp = (LAYER == 0) ? g_w1l : g_w2l;
    const float* __restrict__ dmod = (LAYER == 0) ? g_demod1 : g_demod2;

    if (tid < 8) ((uint4*)smem)[tid] = make_uint4(0, 0, 0, 0);

    // ---- loaders ----
    auto loadW = [&](int tap2, int ch2, int buf) {
        const int row = tid >> 1, half = tid & 1;
        const size_t gs = (size_t)(co0 + row)*KTOT + tap2*256 + ch2*32 + half*16;
        uint32_t d = sb + WT_OFF + buf*WT_STG + row*64 + half*32;
        cp16(d,              Whp + gs);
        cp16(d + 16,         Whp + gs + 8);
        cp16(d + WT_LO,      Wlp + gs);
        cp16(d + WT_LO + 16, Wlp + gs + 8);
    };
    auto loadActPart = [&](int ch2, int part) {
        const uint32_t ab = sb + ACT_OFF + (ch2 & 1)*ACT_STG;
        const int j = tid & 3;
        for (int rr = tid >> 2; rr < 65; rr += 64) {
            int r = part*65 + rr;
            if (r >= 258) break;
            int pp = pxt - 65 + r;
            bool ok = (pp >= 0) && (pp < IMG);
            const size_t gs = ((size_t)(b*IMG + (ok ? pp : 0)))*256 + ch2*32 + j*8;
            uint32_t sz = ok ? 16u : 0u;
            uint32_t d = ab + r*64 + j*16;
            cp16z(d,          Ahp + gs, sz);
            cp16z(d + ACT_LO, Alp + gs, sz);
        }
    };

    // prologue
    loadW(0, 0, 0);
#pragma unroll
    for (int p = 0; p < 4; ++p) loadActPart(0, p);
    CP_COMMIT(); CP_WAIT0(); __syncthreads();

    float c[4][4][4];
#pragma unroll
    for (int i = 0; i < 4; ++i)
#pragma unroll
        for (int j = 0; j < 4; ++j)
#pragma unroll
            for (int q = 0; q < 4; ++q) c[i][j][q] = 0.f;

    const int lrow = lid & 15;
    const uint32_t ch16 = (uint32_t)((lid >> 4) << 4);

    int it = 0;
    for (int chunk = 0; chunk < 8; ++chunk) {
        const uint32_t abuf = sb + ACT_OFF + (chunk & 1)*ACT_STG;
        for (int tap = 0; tap < 9; ++tap, ++it) {
            // prefetch
            int ntap = tap + 1, nch = chunk;
            if (ntap == 9) { ntap = 0; nch = chunk + 1; }
            if (nch < 8) loadW(ntap, nch, (it + 1) & 1);
            if (tap < 4 && chunk < 7) loadActPart(chunk + 1, tap);
            CP_COMMIT();

            const int dy = tap / 3 - 1;
            const int dx = tap - (tap / 3)*3 - 1;
            const uint32_t wbuf = sb + WT_OFF + (it & 1)*WT_STG;

            // activation fragment row addresses (with halo shift + validity)
            auto actAddr = [&](int pr, uint32_t& hi, uint32_t& lo) {
                int x  = pr & 63;
                int pp = pxt + pr + dy*64 + dx;
                bool ok = !((x == 0 && dx < 0) || (x == 63 && dx > 0))
                          && (pp >= 0) && (pp < IMG);
                if (ok) {
                    hi = abuf + (uint32_t)(pr + 65 + dy*64 + dx)*64 + ch16;
                    lo = hi + ACT_LO;
                } else {
                    hi = sb + ch16;
                    lo = hi;
                }
            };

            if (LAYER == 1) {
                // M = co (weights are A), N = px (act is B)
                const int wco = wid & 1, wpx = wid >> 1;
                uint32_t aH[4], aL[4];
#pragma unroll
                for (int i = 0; i < 4; ++i) {
                    int r = wco*64 + i*16 + lrow;
                    aH[i] = wbuf + r*64 + ch16;
                    aL[i] = aH[i] + WT_LO;
                }
                uint32_t bH[2], bL[2];
#pragma unroll
                for (int g = 0; g < 2; ++g)
                    actAddr(wpx*32 + g*16 + lrow, bH[g], bL[g]);

#pragma unroll
                for (int s = 0; s < 2; ++s) {
                    const uint32_t so = (uint32_t)(s << 5);
                    uint32_t Bh[2][4], Bl[2][4];
#pragma unroll
                    for (int g = 0; g < 2; ++g) { LDSM4(Bh[g], bH[g] + so); LDSM4(Bl[g], bL[g] + so); }
#pragma unroll
                    for (int i = 0; i < 4; ++i) {
                        uint32_t Ah[4], Al[4];
                        LDSM4(Ah, aH[i] + so); LDSM4(Al, aL[i] + so);
#pragma unroll
                        for (int j = 0; j < 4; ++j) {
                            const int g = j >> 1, o = j & 1;
                            MMA16816(c[i][j], Ah, Bh[g][o], Bh[g][o + 2]);
                            MMA16816(c[i][j], Ah, Bl[g][o], Bl[g][o + 2]);
                            MMA16816(c[i][j], Al, Bh[g][o], Bh[g][o + 2]);
                        }
                    }
                }
            } else {
                // M = px (act is A), N = co (weights are B)
                const int wm = wid & 1, wn = wid >> 1;
                uint32_t aH[4], aL[4];
#pragma unroll
                for (int i = 0; i < 4; ++i)
                    actAddr(wm*64 + i*16 + lrow, aH[i], aL[i]);
                uint32_t bH[2], bL[2];
#pragma unroll
                for (int g = 0; g < 2; ++g) {
                    int r = wn*32 + g*16 + lrow;
                    bH[g] = wbuf + r*64 + ch16;
                    bL[g] = bH[g] + WT_LO;
                }
#pragma unroll
                for (int s = 0; s < 2; ++s) {
                    const uint32_t so = (uint32_t)(s << 5);
                    uint32_t Bh[2][4], Bl[2][4];
#pragma unroll
                    for (int g = 0; g < 2; ++g) { LDSM4(Bh[g], bH[g] + so); LDSM4(Bl[g], bL[g] + so); }
#pragma unroll
                    for (int i = 0; i < 4; ++i) {
                        uint32_t Ah[4], Al[4];
                        LDSM4(Ah, aH[i] + so); LDSM4(Al, aL[i] + so);
#pragma unroll
                        for (int j = 0; j < 4; ++j) {
                            const int g = j >> 1, o = j & 1;
                            MMA16816(c[i][j], Ah, Bh[g][o], Bh[g][o + 2]);
                            MMA16816(c[i][j], Ah, Bl[g][o], Bl[g][o + 2]);
                            MMA16816(c[i][j], Al, Bh[g][o], Bh[g][o + 2]);
                        }
                    }
                }
            }
            CP_WAIT0();
            __syncthreads();
        }
    }

    // ---------------- epilogue ----------------
    const float* nzrow = noise + (size_t)b*IMG;
    if (LAYER == 1) {
        const int wco = wid & 1, wpx = wid >> 1;
#pragma unroll
        for (int i = 0; i < 4; ++i) {
#pragma unroll
            for (int h = 0; h < 2; ++h) {
                const int co = co0 + wco*64 + i*16 + (lid >> 2) + h*8;
                const float dm  = __ldg(&dmod[b*256 + co]);
                const float nwv = __ldg(&nw[co]);
                float* orow = out + (size_t)(b*256 + co)*IMG;
#pragma unroll
                for (int j = 0; j < 4; ++j) {
                    const int px = pxt + wpx*32 + j*8 + (lid & 3)*2;
                    float v0 = dm*c[i][j][h*2 + 0] + nwv*__ldg(&nzrow[px]);
                    float v1 = dm*c[i][j][h*2 + 1] + nwv*__ldg(&nzrow[px + 1]);
                    v0 = (v0 > 0.f) ? v0 : 0.2f*v0;
                    v1 = (v1 > 0.f) ? v1 : 0.2f*v1;
                    *(float2*)(orow + px) = make_float2(v0, v1);
                }
            }
        }
    } else {
        const int wm = wid & 1, wn = wid >> 1;
#pragma unroll
        for (int i = 0; i < 4; ++i) {
#pragma unroll
            for (int q = 0; q < 2; ++q) {
                const int px_r = pxt + wm*64 + i*16 + (lid >> 2) + q*8;
                const float nzv = __ldg(&nzrow[px_r]);
                __nv_bfloat16* dh = g_hh + (size_t)(b*IMG + px_r)*256 + co0;
                __nv_bfloat16* dl = g_hl + (size_t)(b*IMG + px_r)*256 + co0;
#pragma unroll
                for (int j = 0; j < 4; ++j) {
                    const int cl = wn*32 + j*8 + (lid & 3)*2;   // local co (even)
                    const int co = co0 + cl;
                    float2 dm2 = *(float2*)&dmod[b*256 + co];
                    float2 nw2 = *(float2*)&nw[co];
                    float2 s22 = *(float2*)&g_style2[b*256 + co];
                    float v0 = dm2.x*c[i][j][q*2 + 0] + nw2.x*nzv;
                    float v1 = dm2.y*c[i][j][q*2 + 1] + nw2.y*nzv;
                    v0 = ((v0 > 0.f) ? v0 : 0.2f*v0) * s22.x;
                    v1 = ((v1 > 0.f) ? v1 : 0.2f*v1) * s22.y;
                    __nv_bfloat16 h0 = __float2bfloat16(v0);
                    __nv_bfloat16 h1 = __float2bfloat16(v1);
                    __nv_bfloat16 l0 = __float2bfloat16(v0 - __bfloat162float(h0));
                    __nv_bfloat16 l1 = __float2bfloat16(v1 - __bfloat162float(h1));
                    *(__nv_bfloat162*)(dh + cl) = __nv_bfloat162(h0, h1);
                    *(__nv_bfloat162*)(dl + cl) = __nv_bfloat162(l0, l1);
                }
            }
        }
    }
}

// ---------------- launch ----------------
extern "C" void kernel_launch(void* const* d_in, const int* in_sizes, int n_in,
                              void* d_out, int out_size) {
    const float* x       = (const float*)d_in[0];
    const float* w1      = (const float*)d_in[1];
    const float* w2      = (const float*)d_in[2];
    const float* noise1  = (const float*)d_in[3];
    const float* noise2  = (const float*)d_in[4];
    const float* s1_w    = (const float*)d_in[5];
    const float* s1_b    = (const float*)d_in[6];
    const float* conv1_w = (const float*)d_in[7];
    const float* nw1     = (const float*)d_in[8];
    const float* s2_w    = (const float*)d_in[9];
    const float* s2_b    = (const float*)d_in[10];
    const float* conv2_w = (const float*)d_in[11];
    const float* nw2     = (const float*)d_in[12];
    float* out = (float*)d_out;

    cudaFuncSetAttribute(conv_hmma<0>, cudaFuncAttributeMaxDynamicSharedMemorySize, SMEM_TOTAL);
    cudaFuncSetAttribute(conv_hmma<1>, cudaFuncAttributeMaxDynamicSharedMemorySize, SMEM_TOTAL);

    style_kernel<0><<<16, 256>>>(w1, s1_w, s1_b);
    style_kernel<1><<<16, 256>>>(w2, s2_w, s2_b);
    wsq_kernel<0><<<256, 256>>>(conv1_w);
    wsq_kernel<1><<<256, 256>>>(conv2_w);
    demod_kernel<0><<<16, 256>>>();
    demod_kernel<1><<<16, 256>>>();
    wcv_kernel<0><<<2304, 256>>>(conv1_w);
    wcv_kernel<1><<<2304, 256>>>(conv2_w);
    xt_kernel<<<dim3(64, 4, 16), 256>>>(x);

    dim3 grid(32, 2, 16);  // px tiles (128), co tiles (128), batch
    conv_hmma<0><<<grid, 256, SMEM_TOTAL>>>(noise1, nw1, nullptr);
    conv_hmma<1><<<grid, 256, SMEM_TOTAL>>>(noise2, nw2, out);
}

// round 16
// speedup vs baseline: 1.2250x; 1.2250x over previous
#include <cuda_runtime.h>
#include <cuda_bf16.h>
#include <cstdint>

#define BB   16
#define CC   256
#define IMG  4096
#define KTOT 2304

// ---------------- device scratch ----------------
__device__ float g_style1[BB*CC], g_style2[BB*CC];
__device__ float g_demod1[BB*CC], g_demod2[BB*CC];
__device__ float g_wsq1[CC*CC],  g_wsq2[CC*CC];           // [ci][co] sum_t w^2
__device__ __nv_bfloat16 g_w1h[CC*KTOT], g_w1l[CC*KTOT];  // [co][tap*256+ci]
__device__ __nv_bfloat16 g_w2h[CC*KTOT], g_w2l[CC*KTOT];
__device__ __nv_bfloat16 g_xh[(size_t)BB*IMG*CC], g_xl[(size_t)BB*IMG*CC]; // [b][px][ci]
__device__ __nv_bfloat16 g_hh[(size_t)BB*IMG*CC], g_hl[(size_t)BB*IMG*CC];

// ---------------- helpers ----------------
__device__ __forceinline__ uint32_t smem_u32(const void* p) {
    uint32_t a;
    asm("{ .reg .u64 t; cvta.to.shared.u64 t, %1; cvt.u32.u64 %0, t; }" : "=r"(a) : "l"(p));
    return a;
}
__device__ __forceinline__ void cp16(uint32_t dst, const void* src) {
    asm volatile("cp.async.cg.shared.global [%0], [%1], 16;" :: "r"(dst), "l"(src) : "memory");
}
__device__ __forceinline__ void cp16z(uint32_t dst, const void* src, uint32_t sz) {
    asm volatile("cp.async.cg.shared.global [%0], [%1], 16, %2;" :: "r"(dst), "l"(src), "r"(sz) : "memory");
}
#define CP_COMMIT() asm volatile("cp.async.commit_group;" ::: "memory")
#define CP_WAIT0()  asm volatile("cp.async.wait_group 0;" ::: "memory")

#define LDSM4(r, a) \
    asm volatile("ldmatrix.sync.aligned.m8n8.x4.shared.b16 {%0,%1,%2,%3}, [%4];" \
        : "=r"((r)[0]), "=r"((r)[1]), "=r"((r)[2]), "=r"((r)[3]) : "r"(a))

#define MMA16816(c, a, b0, b1) \
    asm volatile("mma.sync.aligned.m16n8k16.row.col.f32.bf16.bf16.f32 " \
        "{%0,%1,%2,%3},{%4,%5,%6,%7},{%8,%9},{%0,%1,%2,%3};" \
        : "+f"((c)[0]), "+f"((c)[1]), "+f"((c)[2]), "+f"((c)[3]) \
        : "r"((a)[0]), "r"((a)[1]), "r"((a)[2]), "r"((a)[3]), "r"(b0), "r"(b1))

// ---------------- style = (w/32) @ s_w^T + s_b ----------------
template<int L>
__global__ void style_kernel(const float* __restrict__ wv, const float* __restrict__ sw,
                             const float* __restrict__ sb) {
    const int b = blockIdx.x, c = threadIdx.x;
    __shared__ float sv[512];
    sv[c] = wv[b*512 + c]; sv[c+256] = wv[b*512 + 256 + c];
    __syncthreads();
    float acc = 0.f;
    const float4* row = (const float4*)(sw + (size_t)c*512);
#pragma unroll 8
    for (int q = 0; q < 128; ++q) {
        float4 w4 = row[q];
        acc += w4.x*sv[4*q] + w4.y*sv[4*q+1] + w4.z*sv[4*q+2] + w4.w*sv[4*q+3];
    }
    (L == 0 ? g_style1 : g_style2)[b*256 + c] = acc * 0.03125f + sb[c];
}

// ---------------- wsq[ci][co] = sum_t w[co][ci][t]^2 ----------------
template<int L>
__global__ void wsq_kernel(const float* __restrict__ w) {
    int co = blockIdx.x, ci = threadIdx.x;
    const float* p = w + (size_t)co*KTOT + ci*9;
    float a = 0.f;
#pragma unroll
    for (int t = 0; t < 9; ++t) a += p[t]*p[t];
    (L == 0 ? g_wsq1 : g_wsq2)[ci*256 + co] = a;
}

// ---------------- demod ----------------
template<int L>
__global__ void demod_kernel() {
    const float* style = (L == 0) ? g_style1 : g_style2;
    const float* wsq   = (L == 0) ? g_wsq1   : g_wsq2;
    float*       dm    = (L == 0) ? g_demod1 : g_demod2;
    const int b = blockIdx.x, co = threadIdx.x;
    __shared__ float s2[256];
    float sv = style[b*256 + co];
    s2[co] = sv*sv;
    __syncthreads();
    float acc = 0.f;
    for (int ci = 0; ci < 256; ++ci) acc += s2[ci] * wsq[ci*256 + co];
    dm[b*256 + co] = rsqrtf(acc + 1e-8f);
}

// ---------------- weight convert: [co][ci*9+tap] -> bf16 hi/lo [co][tap*256+ci] ----
template<int L>
__global__ void wcv_kernel(const float* __restrict__ w) {
    int i = blockIdx.x*256 + threadIdx.x;
    int co = i / KTOT;
    int r  = i - co*KTOT;
    int tap = r >> 8, ci = r & 255;
    float v = w[(size_t)co*KTOT + ci*9 + tap];
    __nv_bfloat16 h = __float2bfloat16(v);
    (L == 0 ? g_w1h : g_w2h)[i] = h;
    (L == 0 ? g_w1l : g_w2l)[i] = __float2bfloat16(v - __bfloat162float(h));
}

// ---------------- x transpose + modulate + bf16 split -> [b][px][ci] ----------------
__global__ void xt_kernel(const float* __restrict__ x) {
    __shared__ float s[64][65];
    const int px0 = blockIdx.x << 6, ci0 = blockIdx.y << 6, b = blockIdx.z;
    const int t = threadIdx.x;
    for (int i = t; i < 1024; i += 256) {
        int ci = i >> 4, q = i & 15;
        float4 v = ((const float4*)(x + (size_t)(b*CC + ci0 + ci)*IMG + px0))[q];
        float st = g_style1[b*CC + ci0 + ci];
        s[ci][q*4+0] = v.x*st; s[ci][q*4+1] = v.y*st;
        s[ci][q*4+2] = v.z*st; s[ci][q*4+3] = v.w*st;
    }
    __syncthreads();
    const int px_l = t >> 2, seg = t & 3;
    __align__(16) __nv_bfloat16 hb[16], lb[16];
#pragma unroll
    for (int k = 0; k < 16; ++k) {
        float v = s[seg*16 + k][px_l];
        __nv_bfloat16 h = __float2bfloat16(v);
        hb[k] = h;
        lb[k] = __float2bfloat16(v - __bfloat162float(h));
    }
    size_t o = (size_t)(b*IMG + px0 + px_l)*256 + ci0 + seg*16;
    ((uint4*)(g_xh + o))[0] = ((const uint4*)hb)[0];
    ((uint4*)(g_xh + o))[1] = ((const uint4*)hb)[1];
    ((uint4*)(g_xl + o))[0] = ((const uint4*)lb)[0];
    ((uint4*)(g_xl + o))[1] = ((const uint4*)lb)[1];
}

// ================= HMMA implicit-GEMM conv3x3 =================
// CTA: 128 co x 256 px, 8 warps, warp tile 64x64. K = 4 chunks of 64 ci x 9 taps.
// smem: [0,128) zero row
//       WT_OFF: W double buffer, stage = hi 16K + lo 16K (rows 128B, swizzled)
//       ACT_OFF: act halo single buffer, 386 rows x 128B, hi + lo
#define WT_OFF   1024
#define WT_STG   32768
#define WT_LO    16384
#define ACT_OFF  (WT_OFF + 2*WT_STG)              // 66560
#define ACT_LO   49408
#define SMEM_TOTAL (ACT_OFF + 2*ACT_LO)           // 165376

template<int LAYER>
__global__ void __launch_bounds__(256, 1)
conv_hmma(const float* __restrict__ noise, const float* __restrict__ nw,
          float* __restrict__ out) {
    extern __shared__ __align__(1024) char smem[];
    const uint32_t sb = smem_u32(smem);
    const int tid = threadIdx.x, lid = tid & 31, wid = tid >> 5;

    const int pxt = blockIdx.x << 8;     // 256-px tile
    const int co0 = blockIdx.y << 7;     // 128-co tile
    const int b   = blockIdx.z;

    // warp roles: 4 warps along px (64 each), 2 along co (64 each)
    const int wpx = (LAYER == 0) ? (wid & 3) : (wid >> 1);
    const int wco = (LAYER == 0) ? (wid >> 2) : (wid & 1);

    const __nv_bfloat16* __restrict__ Ahp = (LAYER == 0) ? g_xh  : g_hh;
    const __nv_bfloat16* __restrict__ Alp = (LAYER == 0) ? g_xl  : g_hl;
    const __nv_bfloat16* __restrict__ Whp = (LAYER == 0) ? g_w1h : g_w2h;
    const __nv_bfloat16* __restrict__ Wlp = (LAYER == 0) ? g_w1l : g_w2l;
    const float* __restrict__ dmod = (LAYER == 0) ? g_demod1 : g_demod2;

    if (tid < 8) ((uint4*)smem)[tid] = make_uint4(0, 0, 0, 0);

    // ---- loaders ----
    auto loadW = [&](int tap2, int ch2, int buf) {
        const int row = tid >> 1, half = tid & 1;
        const size_t gs = (size_t)(co0 + row)*KTOT + tap2*256 + ch2*64 + half*32;
        const uint32_t swz = (uint32_t)((row & 7) << 4);
        const uint32_t dbase = sb + WT_OFF + buf*WT_STG + row*128;
#pragma unroll
        for (int j = 0; j < 4; ++j) {
            uint32_t cb = (uint32_t)(half*64 + j*16) ^ swz;
            cp16(dbase + cb,         Whp + gs + j*8);
            cp16(dbase + WT_LO + cb, Wlp + gs + j*8);
        }
    };
    auto loadAct = [&](int ch2) {
        for (int r = tid; r < 386; r += 256) {
            int pp = pxt - 65 + r;
            bool ok = (pp >= 0) && (pp < IMG);
            const size_t gs = ((size_t)(b*IMG + (ok ? pp : 0)))*256 + ch2*64;
            uint32_t sz = ok ? 16u : 0u;
            const uint32_t swz = (uint32_t)((r & 7) << 4);
            const uint32_t dbase = sb + ACT_OFF + r*128;
#pragma unroll
            for (int j = 0; j < 8; ++j) {
                uint32_t cb = (uint32_t)(j*16) ^ swz;
                cp16z(dbase + cb,          Ahp + gs + j*8, sz);
                cp16z(dbase + ACT_LO + cb, Alp + gs + j*8, sz);
            }
        }
    };

    // prologue
    loadW(0, 0, 0);
    loadAct(0);
    CP_COMMIT(); CP_WAIT0(); __syncthreads();

    float c[4][8][4];
#pragma unroll
    for (int i = 0; i < 4; ++i)
#pragma unroll
        for (int j = 0; j < 8; ++j)
#pragma unroll
            for (int q = 0; q < 4; ++q) c[i][j][q] = 0.f;

    const int lrow = lid & 15;
    const uint32_t lhi = (uint32_t)((lid >> 4) << 4);

    int it = 0;
    for (int chunk = 0; chunk < 4; ++chunk) {
        for (int tap = 0; tap < 9; ++tap, ++it) {
            if (tap < 8) loadW(tap + 1, chunk, (it + 1) & 1);
            CP_COMMIT();

            const int dy = tap / 3 - 1;
            const int dx = tap - (tap / 3)*3 - 1;
            const uint32_t wbuf = sb + WT_OFF + (it & 1)*WT_STG;

            // act fragment descriptors (4 frags of 16 px rows)
            uint32_t xb[4], xswz[4], xlo[4];
#pragma unroll
            for (int f = 0; f < 4; ++f) {
                int pr = wpx*64 + f*16 + lrow;
                int x  = pr & 63;
                int pp = pxt + pr + dy*64 + dx;
                bool ok = !((x == 0 && dx < 0) || (x == 63 && dx > 0))
                          && (pp >= 0) && (pp < IMG);
                int r  = pr + 65 + dy*64 + dx;
                xb[f]   = ok ? (sb + ACT_OFF + (uint32_t)r*128) : sb;
                xswz[f] = ok ? (uint32_t)((r & 7) << 4) : 0u;
                xlo[f]  = ok ? (uint32_t)ACT_LO : 0u;
            }
            // weight fragment descriptors
            uint32_t wb[4], wsz[4];
#pragma unroll
            for (int f = 0; f < 4; ++f) {
                int r = wco*64 + f*16 + lrow;
                wb[f]  = wbuf + r*128;
                wsz[f] = (uint32_t)((r & 7) << 4);
            }

#pragma unroll
            for (int s = 0; s < 4; ++s) {
                const uint32_t colx = (uint32_t)(s << 5) | lhi;
                uint32_t Bh[4][4], Bl[4][4];
                if (LAYER == 1) {   // B = act (px = N)
#pragma unroll
                    for (int f = 0; f < 4; ++f) {
                        uint32_t a0 = xb[f] + (colx ^ xswz[f]);
                        LDSM4(Bh[f], a0); LDSM4(Bl[f], a0 + xlo[f]);
                    }
                } else {            // B = weights (co = N)
#pragma unroll
                    for (int f = 0; f < 4; ++f) {
                        uint32_t a0 = wb[f] + (colx ^ wsz[f]);
                        LDSM4(Bh[f], a0); LDSM4(Bl[f], a0 + WT_LO);
                    }
                }
#pragma unroll
                for (int i = 0; i < 4; ++i) {
                    uint32_t Ah[4], Al[4];
                    if (LAYER == 1) {   // A = weights (co = M)
                        uint32_t a0 = wb[i] + (colx ^ wsz[i]);
                        LDSM4(Ah, a0); LDSM4(Al, a0 + WT_LO);
                    } else {            // A = act (px = M)
                        uint32_t a0 = xb[i] + (colx ^ xswz[i]);
                        LDSM4(Ah, a0); LDSM4(Al, a0 + xlo[i]);
                    }
#pragma unroll
                    for (int j = 0; j < 8; ++j) {
                        const int g = j >> 1, o = j & 1;
                        MMA16816(c[i][j], Ah, Bh[g][o], Bh[g][o + 2]);
                        MMA16816(c[i][j], Ah, Bl[g][o], Bl[g][o + 2]);
                        MMA16816(c[i][j], Al, Bh[g][o], Bh[g][o + 2]);
                    }
                }
            }
            CP_WAIT0();
            __syncthreads();
        }
        if (chunk < 3) {
            loadAct(chunk + 1);
            loadW(0, chunk + 1, it & 1);
            CP_COMMIT(); CP_WAIT0(); __syncthreads();
        }
    }

    // ---------------- epilogue ----------------
    const float* nzrow = noise + (size_t)b*IMG;
    if (LAYER == 1) {
        // c[i=co frag][j=px frag]; write fp32 [co][px]
#pragma unroll
        for (int i = 0; i < 4; ++i) {
#pragma unroll
            for (int h = 0; h < 2; ++h) {
                const int co = co0 + wco*64 + i*16 + (lid >> 2) + h*8;
                const float dm  = __ldg(&dmod[b*256 + co]);
                const float nwv = __ldg(&nw[co]);
                float* orow = out + (size_t)(b*256 + co)*IMG;
#pragma unroll
                for (int j = 0; j < 8; ++j) {
                    const int px = pxt + wpx*64 + j*8 + (lid & 3)*2;
                    float2 nz = *(const float2*)(nzrow + px);
                    float v0 = dm*c[i][j][h*2 + 0] + nwv*nz.x;
                    float v1 = dm*c[i][j][h*2 + 1] + nwv*nz.y;
                    v0 = (v0 > 0.f) ? v0 : 0.2f*v0;
                    v1 = (v1 > 0.f) ? v1 : 0.2f*v1;
                    *(float2*)(orow + px) = make_float2(v0, v1);
                }
            }
        }
    } else {
        // c[i=px frag][j=co frag]; write bf16 hi/lo [px][ci] with style2 folded
#pragma unroll
        for (int i = 0; i < 4; ++i) {
#pragma unroll
            for (int q = 0; q < 2; ++q) {
                const int px_r = pxt + wpx*64 + i*16 + (lid >> 2) + q*8;
                const float nzv = __ldg(&nzrow[px_r]);
                __nv_bfloat16* dh = g_hh + (size_t)(b*IMG + px_r)*256 + co0;
                __nv_bfloat16* dl = g_hl + (size_t)(b*IMG + px_r)*256 + co0;
#pragma unroll
                for (int j = 0; j < 8; ++j) {
                    const int cl = wco*64 + j*8 + (lid & 3)*2;
                    const int co = co0 + cl;
                    float2 dm2 = *(const float2*)&dmod[b*256 + co];
                    float2 nw2 = *(const float2*)&nw[co];
                    float2 s22 = *(const float2*)&g_style2[b*256 + co];
                    float v0 = dm2.x*c[i][j][q*2 + 0] + nw2.x*nzv;
                    float v1 = dm2.y*c[i][j][q*2 + 1] + nw2.y*nzv;
                    v0 = ((v0 > 0.f) ? v0 : 0.2f*v0) * s22.x;
                    v1 = ((v1 > 0.f) ? v1 : 0.2f*v1) * s22.y;
                    __nv_bfloat16 h0 = __float2bfloat16(v0);
                    __nv_bfloat16 h1 = __float2bfloat16(v1);
                    __nv_bfloat16 l0 = __float2bfloat16(v0 - __bfloat162float(h0));
                    __nv_bfloat16 l1 = __float2bfloat16(v1 - __bfloat162float(h1));
                    *(__nv_bfloat162*)(dh + cl) = __nv_bfloat162(h0, h1);
                    *(__nv_bfloat162*)(dl + cl) = __nv_bfloat162(l0, l1);
                }
            }
        }
    }
}

// ---------------- launch ----------------
extern "C" void kernel_launch(void* const* d_in, const int* in_sizes, int n_in,
                              void* d_out, int out_size) {
    const float* x       = (const float*)d_in[0];
    const float* w1      = (const float*)d_in[1];
    const float* w2      = (const float*)d_in[2];
    const float* noise1  = (const float*)d_in[3];
    const float* noise2  = (const float*)d_in[4];
    const float* s1_w    = (const float*)d_in[5];
    const float* s1_b    = (const float*)d_in[6];
    const float* conv1_w = (const float*)d_in[7];
    const float* nw1     = (const float*)d_in[8];
    const float* s2_w    = (const float*)d_in[9];
    const float* s2_b    = (const float*)d_in[10];
    const float* conv2_w = (const float*)d_in[11];
    const float* nw2     = (const float*)d_in[12];
    float* out = (float*)d_out;

    cudaFuncSetAttribute(conv_hmma<0>, cudaFuncAttributeMaxDynamicSharedMemorySize, SMEM_TOTAL);
    cudaFuncSetAttribute(conv_hmma<1>, cudaFuncAttributeMaxDynamicSharedMemorySize, SMEM_TOTAL);

    style_kernel<0><<<16, 256>>>(w1, s1_w, s1_b);
    style_kernel<1><<<16, 256>>>(w2, s2_w, s2_b);
    wsq_kernel<0><<<256, 256>>>(conv1_w);
    wsq_kernel<1><<<256, 256>>>(conv2_w);
    demod_kernel<0><<<16, 256>>>();
    demod_kernel<1><<<16, 256>>>();
    wcv_kernel<0><<<2304, 256>>>(conv1_w);
    wcv_kernel<1><<<2304, 256>>>(conv2_w);
    xt_kernel<<<dim3(64, 4, 16), 256>>>(x);

    dim3 grid(16, 2, 16);  // px tiles (256), co tiles (128), batch
    conv_hmma<0><<<grid, 256, SMEM_TOTAL>>>(noise1, nw1, nullptr);
    conv_hmma<1><<<grid, 256, SMEM_TOTAL>>>(noise2, nw2, out);
}

// round 17
// speedup vs baseline: 1.8155x; 1.4820x over previous
#include <cuda_runtime.h>
#include <cuda_fp16.h>
#include <cstdint>

#define BB   16
#define CC   256
#define IMG  4096
#define KTOT 2304

// ---------------- device scratch ----------------
__device__ float g_style1[BB*CC], g_style2[BB*CC];
__device__ float g_demod1[BB*CC], g_demod2[BB*CC];
__device__ float g_wsq1[CC*CC],  g_wsq2[CC*CC];        // [ci][co] sum_t w^2
__device__ __half g_w1h[CC*KTOT], g_w1l[CC*KTOT];      // [co][tap*256+ci] fp16 hi/lo
__device__ __half g_w2h[CC*KTOT], g_w2l[CC*KTOT];
__device__ __half g_xf[(size_t)BB*IMG*CC];             // [b][px][ci] fp16
__device__ __half g_hf[(size_t)BB*IMG*CC];

// ---------------- helpers ----------------
__device__ __forceinline__ uint32_t smem_u32(const void* p) {
    uint32_t a;
    asm("{ .reg .u64 t; cvta.to.shared.u64 t, %1; cvt.u32.u64 %0, t; }" : "=r"(a) : "l"(p));
    return a;
}
__device__ __forceinline__ void cp16(uint32_t dst, const void* src) {
    asm volatile("cp.async.cg.shared.global [%0], [%1], 16;" :: "r"(dst), "l"(src) : "memory");
}
__device__ __forceinline__ void cp16z(uint32_t dst, const void* src, uint32_t sz) {
    asm volatile("cp.async.cg.shared.global [%0], [%1], 16, %2;" :: "r"(dst), "l"(src), "r"(sz) : "memory");
}
#define CP_COMMIT() asm volatile("cp.async.commit_group;" ::: "memory")
#define CP_WAIT0()  asm volatile("cp.async.wait_group 0;" ::: "memory")

#define LDSM4(r, a) \
    asm volatile("ldmatrix.sync.aligned.m8n8.x4.shared.b16 {%0,%1,%2,%3}, [%4];" \
        : "=r"((r)[0]), "=r"((r)[1]), "=r"((r)[2]), "=r"((r)[3]) : "r"(a))

#define MMA16816(c, a, b0, b1) \
    asm volatile("mma.sync.aligned.m16n8k16.row.col.f32.f16.f16.f32 " \
        "{%0,%1,%2,%3},{%4,%5,%6,%7},{%8,%9},{%0,%1,%2,%3};" \
        : "+f"((c)[0]), "+f"((c)[1]), "+f"((c)[2]), "+f"((c)[3]) \
        : "r"((a)[0]), "r"((a)[1]), "r"((a)[2]), "r"((a)[3]), "r"(b0), "r"(b1))

// ---------------- style = (w/32) @ s_w^T + s_b ----------------
template<int L>
__global__ void style_kernel(const float* __restrict__ wv, const float* __restrict__ sw,
                             const float* __restrict__ sb) {
    const int b = blockIdx.x, c = threadIdx.x;
    __shared__ float sv[512];
    sv[c] = wv[b*512 + c]; sv[c+256] = wv[b*512 + 256 + c];
    __syncthreads();
    float acc = 0.f;
    const float4* row = (const float4*)(sw + (size_t)c*512);
#pragma unroll 8
    for (int q = 0; q < 128; ++q) {
        float4 w4 = row[q];
        acc += w4.x*sv[4*q] + w4.y*sv[4*q+1] + w4.z*sv[4*q+2] + w4.w*sv[4*q+3];
    }
    (L == 0 ? g_style1 : g_style2)[b*256 + c] = acc * 0.03125f + sb[c];
}

// ---------------- wsq[ci][co] = sum_t w[co][ci][t]^2 ----------------
template<int L>
__global__ void wsq_kernel(const float* __restrict__ w) {
    int co = blockIdx.x, ci = threadIdx.x;
    const float* p = w + (size_t)co*KTOT + ci*9;
    float a = 0.f;
#pragma unroll
    for (int t = 0; t < 9; ++t) a += p[t]*p[t];
    (L == 0 ? g_wsq1 : g_wsq2)[ci*256 + co] = a;
}

// ---------------- demod ----------------
template<int L>
__global__ void demod_kernel() {
    const float* style = (L == 0) ? g_style1 : g_style2;
    const float* wsq   = (L == 0) ? g_wsq1   : g_wsq2;
    float*       dm    = (L == 0) ? g_demod1 : g_demod2;
    const int b = blockIdx.x, co = threadIdx.x;
    __shared__ float s2[256];
    float sv = style[b*256 + co];
    s2[co] = sv*sv;
    __syncthreads();
    float acc = 0.f;
    for (int ci = 0; ci < 256; ++ci) acc += s2[ci] * wsq[ci*256 + co];
    dm[b*256 + co] = rsqrtf(acc + 1e-8f);
}

// ---------------- weight convert: [co][ci*9+tap] -> fp16 hi/lo [co][tap*256+ci] ----
template<int L>
__global__ void wcv_kernel(const float* __restrict__ w) {
    int i = blockIdx.x*256 + threadIdx.x;
    int co = i / KTOT;
    int r  = i - co*KTOT;
    int tap = r >> 8, ci = r & 255;
    float v = w[(size_t)co*KTOT + ci*9 + tap];
    __half h = __float2half_rn(v);
    (L == 0 ? g_w1h : g_w2h)[i] = h;
    (L == 0 ? g_w1l : g_w2l)[i] = __float2half_rn(v - __half2float(h));
}

// ---------------- x transpose + modulate + fp16 -> [b][px][ci] ----------------
__global__ void xt_kernel(const float* __restrict__ x) {
    __shared__ float s[64][65];
    const int px0 = blockIdx.x << 6, ci0 = blockIdx.y << 6, b = blockIdx.z;
    const int t = threadIdx.x;
    for (int i = t; i < 1024; i += 256) {
        int ci = i >> 4, q = i & 15;
        float4 v = ((const float4*)(x + (size_t)(b*CC + ci0 + ci)*IMG + px0))[q];
        float st = g_style1[b*CC + ci0 + ci];
        s[ci][q*4+0] = v.x*st; s[ci][q*4+1] = v.y*st;
        s[ci][q*4+2] = v.z*st; s[ci][q*4+3] = v.w*st;
    }
    __syncthreads();
    const int px_l = t >> 2, seg = t & 3;
    __align__(16) __half hb[16];
#pragma unroll
    for (int k = 0; k < 16; ++k) hb[k] = __float2half_rn(s[seg*16 + k][px_l]);
    size_t o = (size_t)(b*IMG + px0 + px_l)*256 + ci0 + seg*16;
    ((uint4*)(g_xf + o))[0] = ((const uint4*)hb)[0];
    ((uint4*)(g_xf + o))[1] = ((const uint4*)hb)[1];
}

// ================= HMMA implicit-GEMM conv3x3 (fp16, 2-term) =================
// CTA: 128 co x 256 px, 8 warps, warp tile 64x64. K = 4 chunks of 64 ci x 9 taps.
// smem: [0,128) zero row
//       WT_OFF: W double buffer, stage = hi 16K + lo 16K (128B rows, swizzled)
//       ACT_OFF: act halo double buffer, stage = 386 rows x 128B (single fp16)
#define WT_OFF   1024
#define WT_STG   32768
#define WT_LO    16384
#define ACT_OFF  (WT_OFF + 2*WT_STG)              // 66560
#define ACT_STG  49408
#define SMEM_TOTAL (ACT_OFF + 2*ACT_STG)          // 165376

template<int LAYER>
__global__ void __launch_bounds__(256, 1)
conv_hmma(const float* __restrict__ noise, const float* __restrict__ nw,
          float* __restrict__ out) {
    extern __shared__ __align__(1024) char smem[];
    const uint32_t sb = smem_u32(smem);
    const int tid = threadIdx.x, lid = tid & 31, wid = tid >> 5;

    const int pxt = blockIdx.x << 8;     // 256-px tile
    const int co0 = blockIdx.y << 7;     // 128-co tile
    const int b   = blockIdx.z;

    const int wpx = (LAYER == 0) ? (wid & 3) : (wid >> 1);
    const int wco = (LAYER == 0) ? (wid >> 2) : (wid & 1);

    const __half* __restrict__ Axp = (LAYER == 0) ? g_xf  : g_hf;
    const __half* __restrict__ Whp = (LAYER == 0) ? g_w1h : g_w2h;
    const __half* __restrict__ Wlp = (LAYER == 0) ? g_w1l : g_w2l;
    const float* __restrict__ dmod = (LAYER == 0) ? g_demod1 : g_demod2;

    if (tid < 8) ((uint4*)smem)[tid] = make_uint4(0, 0, 0, 0);

    // ---- loaders ----
    auto loadW = [&](int tap2, int ch2, int buf) {
        const int row = tid >> 1, half = tid & 1;
        const size_t gs = (size_t)(co0 + row)*KTOT + tap2*256 + ch2*64 + half*32;
        const uint32_t swz = (uint32_t)((row & 7) << 4);
        const uint32_t dbase = sb + WT_OFF + buf*WT_STG + row*128;
#pragma unroll
        for (int j = 0; j < 4; ++j) {
            uint32_t cb = (uint32_t)(half*64 + j*16) ^ swz;
            cp16(dbase + cb,         Whp + gs + j*8);
            cp16(dbase + WT_LO + cb, Wlp + gs + j*8);
        }
    };
    // full act halo load (prologue)
    auto loadAct = [&](int ch2, int buf) {
        for (int r = tid; r < 386; r += 256) {
            int pp = pxt - 65 + r;
            bool ok = (pp >= 0) && (pp < IMG);
            const size_t gs = ((size_t)(b*IMG + (ok ? pp : 0)))*256 + ch2*64;
            uint32_t sz = ok ? 16u : 0u;
            const uint32_t swz = (uint32_t)((r & 7) << 4);
            const uint32_t dbase = sb + ACT_OFF + buf*ACT_STG + r*128;
#pragma unroll
            for (int j = 0; j < 8; ++j)
                cp16z(dbase + ((uint32_t)(j*16) ^ swz), Axp + gs + j*8, sz);
        }
    };
    // quarter act halo load (spread over taps 0..3)
    auto loadActQ = [&](int ch2, int buf, int part) {
        const int r0 = part*97;
        for (int idx = tid; idx < 97*8; idx += 256) {
            int r = r0 + (idx >> 3);
            if (r >= 386) break;
            int j = idx & 7;
            int pp = pxt - 65 + r;
            bool ok = (pp >= 0) && (pp < IMG);
            const size_t gs = ((size_t)(b*IMG + (ok ? pp : 0)))*256 + ch2*64 + j*8;
            uint32_t sz = ok ? 16u : 0u;
            const uint32_t swz = (uint32_t)((r & 7) << 4);
            cp16z(sb + ACT_OFF + buf*ACT_STG + r*128 + ((uint32_t)(j*16) ^ swz),
                  Axp + gs, sz);
        }
    };

    // prologue
    loadW(0, 0, 0);
    loadAct(0, 0);
    CP_COMMIT(); CP_WAIT0(); __syncthreads();

    float c[4][8][4];
#pragma unroll
    for (int i = 0; i < 4; ++i)
#pragma unroll
        for (int j = 0; j < 8; ++j)
#pragma unroll
            for (int q = 0; q < 4; ++q) c[i][j][q] = 0.f;

    const int lrow = lid & 15;
    const uint32_t lhi = (uint32_t)((lid >> 4) << 4);

    int it = 0;
    for (int chunk = 0; chunk < 4; ++chunk) {
        const uint32_t abuf = sb + ACT_OFF + (chunk & 1)*ACT_STG;
        for (int tap = 0; tap < 9; ++tap, ++it) {
            // prefetch: next-tap weights (or next chunk tap0), + act quarters
            if (tap < 8)            loadW(tap + 1, chunk, (it + 1) & 1);
            else if (chunk < 3)     loadW(0, chunk + 1, (it + 1) & 1);
            if (tap < 4 && chunk < 3) loadActQ(chunk + 1, (chunk + 1) & 1, tap);
            CP_COMMIT();

            const int dy = tap / 3 - 1;
            const int dx = tap - (tap / 3)*3 - 1;
            const uint32_t wbuf = sb + WT_OFF + (it & 1)*WT_STG;

            // act fragment descriptors (4 frags of 16 px rows)
            uint32_t xb[4], xswz[4];
#pragma unroll
            for (int f = 0; f < 4; ++f) {
                int pr = ((LAYER == 0) ? wpx : wpx)*64 + f*16 + lrow;
                int x  = pr & 63;
                int pp = pxt + pr + dy*64 + dx;
                bool ok = !((x == 0 && dx < 0) || (x == 63 && dx > 0))
                          && (pp >= 0) && (pp < IMG);
                int r  = pr + 65 + dy*64 + dx;
                xb[f]   = ok ? (abuf + (uint32_t)r*128) : sb;
                xswz[f] = ok ? (uint32_t)((r & 7) << 4) : 0u;
            }
            // weight fragment descriptors
            uint32_t wb[4], wsz[4];
#pragma unroll
            for (int f = 0; f < 4; ++f) {
                int r = wco*64 + f*16 + lrow;
                wb[f]  = wbuf + r*128;
                wsz[f] = (uint32_t)((r & 7) << 4);
            }

#pragma unroll
            for (int s = 0; s < 4; ++s) {
                const uint32_t colx = (uint32_t)(s << 5) | lhi;
                if (LAYER == 0) {
                    // A = act (M=px, single), B = weights hi/lo (N=co)
                    uint32_t Bh[4][4], Bl[4][4];
#pragma unroll
                    for (int f = 0; f < 4; ++f) {
                        uint32_t a0 = wb[f] + (colx ^ wsz[f]);
                        LDSM4(Bh[f], a0); LDSM4(Bl[f], a0 + WT_LO);
                    }
#pragma unroll
                    for (int i = 0; i < 4; ++i) {
                        uint32_t Ax[4];
                        LDSM4(Ax, xb[i] + (colx ^ xswz[i]));
#pragma unroll
                        for (int j = 0; j < 8; ++j) {
                            const int g = j >> 1, o = j & 1;
                            MMA16816(c[i][j], Ax, Bh[g][o], Bh[g][o + 2]);
                            MMA16816(c[i][j], Ax, Bl[g][o], Bl[g][o + 2]);
                        }
                    }
                } else {
                    // A = weights hi/lo (M=co), B = act (N=px, single)
                    uint32_t Bx[4][4];
#pragma unroll
                    for (int f = 0; f < 4; ++f)
                        LDSM4(Bx[f], xb[f] + (colx ^ xswz[f]));
#pragma unroll
                    for (int i = 0; i < 4; ++i) {
                        uint32_t Ah[4], Al[4];
                        uint32_t a0 = wb[i] + (colx ^ wsz[i]);
                        LDSM4(Ah, a0); LDSM4(Al, a0 + WT_LO);
#pragma unroll
                        for (int j = 0; j < 8; ++j) {
                            const int g = j >> 1, o = j & 1;
                            MMA16816(c[i][j], Ah, Bx[g][o], Bx[g][o + 2]);
                            MMA16816(c[i][j], Al, Bx[g][o], Bx[g][o + 2]);
                        }
                    }
                }
            }
            CP_WAIT0();
            __syncthreads();
        }
    }

    // ---------------- epilogue ----------------
    const float* nzrow = noise + (size_t)b*IMG;
    if (LAYER == 1) {
        // c[i=co frag][j=px frag]; write fp32 [co][px]
#pragma unroll
        for (int i = 0; i < 4; ++i) {
#pragma unroll
            for (int h = 0; h < 2; ++h) {
                const int co = co0 + wco*64 + i*16 + (lid >> 2) + h*8;
                const float dm  = __ldg(&dmod[b*256 + co]);
                const float nwv = __ldg(&nw[co]);
                float* orow = out + (size_t)(b*256 + co)*IMG;
#pragma unroll
                for (int j = 0; j < 8; ++j) {
                    const int px = pxt + wpx*64 + j*8 + (lid & 3)*2;
                    float2 nz = *(const float2*)(nzrow + px);
                    float v0 = dm*c[i][j][h*2 + 0] + nwv*nz.x;
                    float v1 = dm*c[i][j][h*2 + 1] + nwv*nz.y;
                    v0 = (v0 > 0.f) ? v0 : 0.2f*v0;
                    v1 = (v1 > 0.f) ? v1 : 0.2f*v1;
                    *(float2*)(orow + px) = make_float2(v0, v1);
                }
            }
        }
    } else {
        // c[i=px frag][j=co frag]; write fp16 [px][ci] with style2 folded
#pragma unroll
        for (int i = 0; i < 4; ++i) {
#pragma unroll
            for (int q = 0; q < 2; ++q) {
                const int px_r = pxt + wpx*64 + i*16 + (lid >> 2) + q*8;
                const float nzv = __ldg(&nzrow[px_r]);
                __half* dh = g_hf + (size_t)(b*IMG + px_r)*256 + co0;
#pragma unroll
                for (int j = 0; j < 8; ++j) {
                    const int cl = wco*64 + j*8 + (lid & 3)*2;
                    const int co = co0 + cl;
                    float2 dm2 = *(const float2*)&dmod[b*256 + co];
                    float2 nw2 = *(const float2*)&nw[co];
                    float2 s22 = *(const float2*)&g_style2[b*256 + co];
                    float v0 = dm2.x*c[i][j][q*2 + 0] + nw2.x*nzv;
                    float v1 = dm2.y*c[i][j][q*2 + 1] + nw2.y*nzv;
                    v0 = ((v0 > 0.f) ? v0 : 0.2f*v0) * s22.x;
                    v1 = ((v1 > 0.f) ? v1 : 0.2f*v1) * s22.y;
                    __half2 hv = __floats2half2_rn(v0, v1);
                    *(__half2*)(dh + cl) = hv;
                }
            }
        }
    }
}

// ---------------- launch ----------------
extern "C" void kernel_launch(void* const* d_in, const int* in_sizes, int n_in,
                              void* d_out, int out_size) {
    const float* x       = (const float*)d_in[0];
    const float* w1      = (const float*)d_in[1];
    const float* w2      = (const float*)d_in[2];
    const float* noise1  = (const float*)d_in[3];
    const float* noise2  = (const float*)d_in[4];
    const float* s1_w    = (const float*)d_in[5];
    const float* s1_b    = (const float*)d_in[6];
    const float* conv1_w = (const float*)d_in[7];
    const float* nw1     = (const float*)d_in[8];
    const float* s2_w    = (const float*)d_in[9];
    const float* s2_b    = (const float*)d_in[10];
    const float* conv2_w = (const float*)d_in[11];
    const float* nw2     = (const float*)d_in[12];
    float* out = (float*)d_out;

    cudaFuncSetAttribute(conv_hmma<0>, cudaFuncAttributeMaxDynamicSharedMemorySize, SMEM_TOTAL);
    cudaFuncSetAttribute(conv_hmma<1>, cudaFuncAttributeMaxDynamicSharedMemorySize, SMEM_TOTAL);

    style_kernel<0><<<16, 256>>>(w1, s1_w, s1_b);
    style_kernel<1><<<16, 256>>>(w2, s2_w, s2_b);
    wsq_kernel<0><<<256, 256>>>(conv1_w);
    wsq_kernel<1><<<256, 256>>>(conv2_w);
    demod_kernel<0><<<16, 256>>>();
    demod_kernel<1><<<16, 256>>>();
    wcv_kernel<0><<<2304, 256>>>(conv1_w);
    wcv_kernel<1><<<2304, 256>>>(conv2_w);
    xt_kernel<<<dim3(64, 4, 16), 256>>>(x);

    dim3 grid(16, 2, 16);  // px tiles (256), co tiles (128), batch
    conv_hmma<0><<<grid, 256, SMEM_TOTAL>>>(noise1, nw1, nullptr);
    conv_hmma<1><<<grid, 256, SMEM_TOTAL>>>(noise2, nw2, out);
}